// round 3
// baseline (speedup 1.0000x reference)
#include <cuda_runtime.h>
#include <cstdint>

#define T_STEPS 1024
#define B_SZ    32
#define I_SZ    512
#define H_SZ    512
#define G4      2048                 // 4*H
#define TBH     (T_STEPS * B_SZ * H_SZ)
#define BH      (B_SZ * H_SZ)
#define NG      4                    // independent batch groups (8 batches each)
#define NC      32                   // CTAs per group
#define WPITCH  516                  // padded smem row pitch (floats)

typedef unsigned long long ull;

// ---------------- device scratch (no allocation allowed) ----------------
__device__ float g_gates[(size_t)T_STEPS * B_SZ * G4];   // [t][b][p], p = 4j+g
__device__ float g_wih_p[G4 * I_SZ];                     // packed W_ih (p = 4j+g)
__device__ float g_whh_p[G4 * H_SZ];                     // packed W_hh (p = 4j+g)
__device__ float g_bias_p[G4];                           // b_ih + b_hh, packed
__device__ float g_hbuf[NG * 2 * 8 * H_SZ];              // [grp][ph][b][j]
__device__ unsigned g_flags[NG * NC];                    // per-CTA step flags

// ---------------- packed f32x2 helpers ----------------
__device__ __forceinline__ void ffma2(ull &d, ull a, ull b) {
    asm("fma.rn.f32x2 %0, %1, %2, %3;" : "=l"(d) : "l"(a), "l"(b), "l"(d));
}
__device__ __forceinline__ void fadd2(ull &d, ull a) {
    asm("add.rn.f32x2 %0, %1, %2;" : "=l"(d) : "l"(d), "l"(a));
}
__device__ __forceinline__ ull pack2(float x) {
    ull r; asm("mov.b64 %0, {%1, %1};" : "=l"(r) : "f"(x)); return r;
}
__device__ __forceinline__ float2 unpack2(ull v) {
    float2 r; asm("mov.b64 {%0, %1}, %2;" : "=f"(r.x), "=f"(r.y) : "l"(v)); return r;
}
__device__ __forceinline__ unsigned ld_acq(const unsigned* p) {
    unsigned v; asm volatile("ld.acquire.gpu.global.u32 %0, [%1];" : "=r"(v) : "l"(p) : "memory");
    return v;
}
__device__ __forceinline__ void st_rel(unsigned* p, unsigned v) {
    asm volatile("st.release.gpu.global.u32 [%0], %1;" :: "l"(p), "r"(v) : "memory");
}

__device__ __forceinline__ float sigf(float x) {
    return __fdividef(1.f, 1.f + __expf(-x));
}
__device__ __forceinline__ float tanh_fast(float x) {
    float ax = fabsf(x);
    float e  = __expf(-2.f * ax);
    float r  = __fdividef(1.f - e, 1.f + e);
    return copysignf(r, x);
}

// ---------------- prep: pack weights, transpose h0, reset flags ----------------
__global__ void prep_kernel(const float* __restrict__ Wih, const float* __restrict__ Whh,
                            const float* __restrict__ bih, const float* __restrict__ bhh,
                            const float* __restrict__ h0) {
    int p = blockIdx.x;                     // packed row p = 4j + g
    int g = p & 3, j = p >> 2;
    int orig = g * H_SZ + j;

    const float* srcI = Wih + (size_t)orig * I_SZ;
    const float* srcH = Whh + (size_t)orig * H_SZ;
    float* dI = g_wih_p + (size_t)p * I_SZ;
    float* dH = g_whh_p + (size_t)p * H_SZ;
    for (int k = threadIdx.x; k < I_SZ; k += blockDim.x) dI[k] = srcI[k];
    for (int k = threadIdx.x; k < H_SZ; k += blockDim.x) dH[k] = srcH[k];
    if (threadIdx.x == 0) g_bias_p[p] = bih[orig] + bhh[orig];

    if (p < H_SZ) {                          // h0 -> g_hbuf[grp][0][b&7][j=p]
        for (int b = threadIdx.x; b < B_SZ; b += blockDim.x)
            g_hbuf[((size_t)(b >> 3) * 2 * 8 + (b & 7)) * H_SZ + p] = h0[(size_t)b * H_SZ + p];
    }
    if (p < NG * NC && threadIdx.x == 0) g_flags[p] = 0;
}

// ---------------- phase 1: gates_x GEMM  C[m][p] = A[m][:] . Wp[p][:] + bias[p] ----------------
#define BM 128
#define BN 64
#define BK 16
#define LDA (BM + 4)
#define LDB (BN + 4)

__global__ __launch_bounds__(256) void gemm_x_kernel(const float* __restrict__ A) {
    __shared__ float sA[BK][LDA];
    __shared__ float sB[BK][LDB];
    int tid   = threadIdx.x;
    int mBase = blockIdx.y * BM;
    int nBase = blockIdx.x * BN;
    int tm = tid & 15, tn = tid >> 4;

    int aM0 = tid >> 2;
    int aK0 = (tid & 3) * 4;
    int bN  = tid >> 2;
    int bK  = (tid & 3) * 4;

    const float* Ag = A + (size_t)mBase * I_SZ;
    const float* Bg = g_wih_p + (size_t)nBase * I_SZ;

    float4 ra0 = *(const float4*)(Ag + (size_t)aM0 * I_SZ + aK0);
    float4 ra1 = *(const float4*)(Ag + (size_t)(aM0 + 64) * I_SZ + aK0);
    float4 rb  = *(const float4*)(Bg + (size_t)bN * I_SZ + bK);

    ull acc[4][4];
#pragma unroll
    for (int u = 0; u < 4; u++)
#pragma unroll
        for (int j = 0; j < 4; j++) acc[u][j] = 0ull;

    const int KT = I_SZ / BK;
    for (int kt = 0; kt < KT; kt++) {
        sA[aK0 + 0][aM0] = ra0.x; sA[aK0 + 1][aM0] = ra0.y;
        sA[aK0 + 2][aM0] = ra0.z; sA[aK0 + 3][aM0] = ra0.w;
        sA[aK0 + 0][aM0 + 64] = ra1.x; sA[aK0 + 1][aM0 + 64] = ra1.y;
        sA[aK0 + 2][aM0 + 64] = ra1.z; sA[aK0 + 3][aM0 + 64] = ra1.w;
        sB[bK + 0][bN] = rb.x; sB[bK + 1][bN] = rb.y;
        sB[bK + 2][bN] = rb.z; sB[bK + 3][bN] = rb.w;
        __syncthreads();

        if (kt + 1 < KT) {
            int k0 = (kt + 1) * BK;
            ra0 = *(const float4*)(Ag + (size_t)aM0 * I_SZ + k0 + aK0);
            ra1 = *(const float4*)(Ag + (size_t)(aM0 + 64) * I_SZ + k0 + aK0);
            rb  = *(const float4*)(Bg + (size_t)bN * I_SZ + k0 + bK);
        }

#pragma unroll
        for (int kk = 0; kk < BK; kk++) {
            ulonglong2 a01 = *(const ulonglong2*)&sA[kk][tm * 8];
            ulonglong2 a23 = *(const ulonglong2*)&sA[kk][tm * 8 + 4];
            float4 b4 = *(const float4*)&sB[kk][tn * 4];
            ull b0 = pack2(b4.x), b1 = pack2(b4.y), b2 = pack2(b4.z), b3 = pack2(b4.w);
            ffma2(acc[0][0], a01.x, b0); ffma2(acc[0][1], a01.x, b1);
            ffma2(acc[0][2], a01.x, b2); ffma2(acc[0][3], a01.x, b3);
            ffma2(acc[1][0], a01.y, b0); ffma2(acc[1][1], a01.y, b1);
            ffma2(acc[1][2], a01.y, b2); ffma2(acc[1][3], a01.y, b3);
            ffma2(acc[2][0], a23.x, b0); ffma2(acc[2][1], a23.x, b1);
            ffma2(acc[2][2], a23.x, b2); ffma2(acc[2][3], a23.x, b3);
            ffma2(acc[3][0], a23.y, b0); ffma2(acc[3][1], a23.y, b1);
            ffma2(acc[3][2], a23.y, b2); ffma2(acc[3][3], a23.y, b3);
        }
        __syncthreads();
    }

    float4 bias = *(const float4*)&g_bias_p[nBase + tn * 4];
    float* C = g_gates + (size_t)(mBase + tm * 8) * G4 + nBase + tn * 4;
#pragma unroll
    for (int u = 0; u < 4; u++) {
        float2 c0 = unpack2(acc[u][0]);
        float2 c1 = unpack2(acc[u][1]);
        float2 c2 = unpack2(acc[u][2]);
        float2 c3 = unpack2(acc[u][3]);
        float4 lo = {c0.x + bias.x, c1.x + bias.y, c2.x + bias.z, c3.x + bias.w};
        float4 hi = {c0.y + bias.x, c1.y + bias.y, c2.y + bias.z, c3.y + bias.w};
        *(float4*)(C + (size_t)(2 * u) * G4)     = lo;
        *(float4*)(C + (size_t)(2 * u + 1) * G4) = hi;
    }
}

// ---------------- phase 2: persistent recurrent scan (flag-synced) ----------------
// 4 groups x 32 CTAs. Group grp owns batches [8g, 8g+8). CTA c owns packed rows
// [64c, 64c+64) (j in [16c, 16c+16)). Thread tid = rq*8 + b: rows {rq, rq+32},
// batch b, FULL K, acc = f32x2 over (k even, k odd). No pack2, no reduction.
// Gates of (jl, b) gathered by warp shuffle from lanes 8g'+b.
__global__ __launch_bounds__(256) void scan_kernel(const float* __restrict__ c0,
                                                   float* __restrict__ out, int out_size) {
    extern __shared__ float smem[];
    float* sh_w = smem;                 // 64 x WPITCH floats
    float* sh_h = smem + 64 * WPITCH;   // 8  x WPITCH floats

    int tid  = threadIdx.x;
    int grp  = blockIdx.x >> 5;
    int c    = blockIdx.x & 31;
    int lane = tid & 31, wid = tid >> 5;
    int rq   = tid >> 3;                // 0..31
    int b    = tid & 7;

    // W_hh slice -> padded SMEM (resident for all 1024 steps)
    {
        const float4* wsrc = (const float4*)(g_whh_p + (size_t)c * 64 * H_SZ);
#pragma unroll
        for (int i = 0; i < 32; i++) {
            int gi = tid + i * 256;          // float4 index, 0..8191
            int r = gi >> 7, k4 = gi & 127;
            *(float4*)(sh_w + r * WPITCH + k4 * 4) = __ldg(wsrc + gi);
        }
    }

    unsigned* flags = g_flags + grp * NC;
    float* hglob = g_hbuf + (size_t)grp * 2 * 8 * H_SZ;

    // epilogue role: lanes 0..15 of each warp each own one (j, b) output
    bool  epi = (lane < 16);
    int   eb  = lane & 7;
    int   ejl = wid + ((lane >> 3) & 1) * 8;   // 0..15
    int   ej  = c * 16 + ejl;
    int   ebg = grp * 8 + eb;
    float c_val = 0.f;
    const float4* gxp = (const float4*)g_gates;
    if (epi) {
        c_val = c0[(size_t)ebg * H_SZ + ej];
        gxp   = (const float4*)(g_gates + (size_t)ebg * G4 + c * 64 + ejl * 4);
    }
    __syncthreads();

    const float* wr0 = sh_w + rq * WPITCH;
    const float* wr1 = sh_w + (rq + 32) * WPITCH;
    const float* hrow = sh_h + b * WPITCH;

    for (int t = 0; t < T_STEPS; t++) {
        // prefetch gates_x (DRAM) before sync — latency covered by poll+compute
        float4 gxv = make_float4(0.f, 0.f, 0.f, 0.f);
        if (epi) gxv = __ldg(gxp + (size_t)t * (B_SZ * G4 / 4));

        // wait for all 32 producers of h[t]: one coalesced 128B acquire-load per poll
        {
            const unsigned* fp = flags + lane;
            for (;;) {
                unsigned v = ld_acq(fp);
                if (__all_sync(0xffffffffu, v >= (unsigned)t)) break;
            }
        }

        // stage h[t] -> padded SMEM (L2-coherent loads)
        {
            const float4* hsrc = (const float4*)(hglob + (t & 1) * (8 * H_SZ));
#pragma unroll
            for (int i = 0; i < 4; i++) {
                int gi = tid + i * 256;      // float4 index, 0..1023
                int hb = gi >> 7, k4 = gi & 127;
                *(float4*)(sh_h + hb * WPITCH + k4 * 4) = __ldcg(hsrc + gi);
            }
        }
        __syncthreads();

        // dot products: rows {rq, rq+32} x batch b over K=512
        ull a00 = 0, a01 = 0, a10 = 0, a11 = 0;
#pragma unroll 8
        for (int k = 0; k < H_SZ; k += 4) {
            ulonglong2 w0 = *(const ulonglong2*)(wr0 + k);
            ulonglong2 w1 = *(const ulonglong2*)(wr1 + k);
            ulonglong2 hh = *(const ulonglong2*)(hrow + k);
            ffma2(a00, hh.x, w0.x); ffma2(a01, hh.y, w0.y);
            ffma2(a10, hh.x, w1.x); ffma2(a11, hh.y, w1.y);
        }
        fadd2(a00, a01); fadd2(a10, a11);
        float2 s1f = unpack2(a00), s2f = unpack2(a10);
        float s1 = s1f.x + s1f.y;     // row rq      (jl = wid,   gate rq&3)
        float s2 = s2f.x + s2f.y;     // row rq + 32 (jl = wid+8, gate rq&3)
        ull sv; asm("mov.b64 %0, {%1, %2};" : "=l"(sv) : "f"(s1), "f"(s2));

        int bl = lane & 7;
        ull q0 = __shfl_sync(0xffffffffu, sv, bl);
        ull q1 = __shfl_sync(0xffffffffu, sv, bl + 8);
        ull q2 = __shfl_sync(0xffffffffu, sv, bl + 16);
        ull q3 = __shfl_sync(0xffffffffu, sv, bl + 24);

        if (epi) {
            bool lo = (lane < 8);
            float2 G0 = unpack2(q0), G1 = unpack2(q1), G2 = unpack2(q2), G3 = unpack2(q3);
            float pi = (lo ? G0.x : G0.y) + gxv.x;
            float pf = (lo ? G1.x : G1.y) + gxv.y;
            float pg = (lo ? G2.x : G2.y) + gxv.z;
            float po = (lo ? G3.x : G3.y) + gxv.w;
            float ig = sigf(pi), fg = sigf(pf), og = sigf(po);
            float gg = tanh_fast(pg);
            c_val = fg * c_val + ig * gg;
            float hn = og * tanh_fast(c_val);
            hglob[((t + 1) & 1) * (8 * H_SZ) + eb * H_SZ + ej] = hn;
            out[(size_t)t * BH + (size_t)ebg * H_SZ + ej] = hn;
            if (t == T_STEPS - 1 && out_size >= TBH + 2 * BH) {
                out[TBH + ebg * H_SZ + ej]      = hn;     // h_f
                out[TBH + BH + ebg * H_SZ + ej] = c_val;  // c_f
            }
        }

        __syncthreads();                      // all warps' h stores done
        if (tid == 0) st_rel(&flags[c], (unsigned)(t + 1));
    }
}

// ---------------- launch ----------------
extern "C" void kernel_launch(void* const* d_in, const int* in_sizes, int n_in,
                              void* d_out, int out_size) {
    const float* input = (const float*)d_in[0];
    const float* h0    = (const float*)d_in[1];
    const float* c0    = (const float*)d_in[2];
    const float* Wih   = (const float*)d_in[3];
    const float* Whh   = (const float*)d_in[4];
    const float* bih   = (const float*)d_in[5];
    const float* bhh   = (const float*)d_in[6];
    float* out = (float*)d_out;

    prep_kernel<<<G4, 128>>>(Wih, Whh, bih, bhh, h0);

    dim3 grid(G4 / BN, (T_STEPS * B_SZ) / BM);
    gemm_x_kernel<<<grid, 256>>>(input);

    const int scan_smem = 72 * WPITCH * (int)sizeof(float);  // 148608 B
    cudaFuncSetAttribute(scan_kernel, cudaFuncAttributeMaxDynamicSharedMemorySize, scan_smem);
    scan_kernel<<<NG * NC, 256, scan_smem>>>(c0, out, out_size);
}

// round 4
// speedup vs baseline: 1.0611x; 1.0611x over previous
#include <cuda_runtime.h>
#include <cstdint>

#define T_STEPS 1024
#define B_SZ    32
#define I_SZ    512
#define H_SZ    512
#define G4      2048                 // 4*H
#define TBH     (T_STEPS * B_SZ * H_SZ)
#define BH      (B_SZ * H_SZ)
#define NG      4                    // independent batch groups (8 batches each)
#define NC      32                   // CTAs per group
#define WPITCH  516                  // padded smem row pitch (floats)

typedef unsigned long long ull;

// ---------------- device scratch (no allocation allowed) ----------------
__device__ float g_gates[(size_t)T_STEPS * B_SZ * G4];   // [t][b][p], p = 4j+g
__device__ float g_wih_p[G4 * I_SZ];                     // packed W_ih (p = 4j+g)
__device__ float g_whh_p[G4 * H_SZ];                     // packed W_hh (p = 4j+g)
__device__ float g_bias_p[G4];                           // b_ih + b_hh, packed
__device__ float g_hbuf[NG * 2 * 8 * H_SZ];              // [grp][ph][b][j]
__device__ unsigned g_flags[NG * NC];                    // per-CTA step flags (128B/group)

// ---------------- packed f32x2 helpers ----------------
__device__ __forceinline__ void ffma2(ull &d, ull a, ull b) {
    asm("fma.rn.f32x2 %0, %1, %2, %3;" : "=l"(d) : "l"(a), "l"(b), "l"(d));
}
__device__ __forceinline__ void fadd2(ull &d, ull a) {
    asm("add.rn.f32x2 %0, %1, %2;" : "=l"(d) : "l"(d), "l"(a));
}
__device__ __forceinline__ ull pack2(float x) {
    ull r; asm("mov.b64 %0, {%1, %1};" : "=l"(r) : "f"(x)); return r;
}
__device__ __forceinline__ float2 unpack2(ull v) {
    float2 r; asm("mov.b64 {%0, %1}, %2;" : "=f"(r.x), "=f"(r.y) : "l"(v)); return r;
}
__device__ __forceinline__ unsigned ld_acq(const unsigned* p) {
    unsigned v; asm volatile("ld.acquire.gpu.global.u32 %0, [%1];" : "=r"(v) : "l"(p) : "memory");
    return v;
}
__device__ __forceinline__ void st_rel(unsigned* p, unsigned v) {
    asm volatile("st.release.gpu.global.u32 [%0], %1;" :: "l"(p), "r"(v) : "memory");
}

__device__ __forceinline__ float sigf(float x) {
    return __fdividef(1.f, 1.f + __expf(-x));
}
__device__ __forceinline__ float tanh_fast(float x) {
    float ax = fabsf(x);
    float e  = __expf(-2.f * ax);
    float r  = __fdividef(1.f - e, 1.f + e);
    return copysignf(r, x);
}

// ---------------- prep: pack weights, transpose h0, reset flags ----------------
__global__ void prep_kernel(const float* __restrict__ Wih, const float* __restrict__ Whh,
                            const float* __restrict__ bih, const float* __restrict__ bhh,
                            const float* __restrict__ h0) {
    int p = blockIdx.x;                     // packed row p = 4j + g
    int g = p & 3, j = p >> 2;
    int orig = g * H_SZ + j;

    const float* srcI = Wih + (size_t)orig * I_SZ;
    const float* srcH = Whh + (size_t)orig * H_SZ;
    float* dI = g_wih_p + (size_t)p * I_SZ;
    float* dH = g_whh_p + (size_t)p * H_SZ;
    for (int k = threadIdx.x; k < I_SZ; k += blockDim.x) dI[k] = srcI[k];
    for (int k = threadIdx.x; k < H_SZ; k += blockDim.x) dH[k] = srcH[k];
    if (threadIdx.x == 0) g_bias_p[p] = bih[orig] + bhh[orig];

    if (p < H_SZ) {                          // h0 -> g_hbuf[grp][0][b&7][j=p]
        for (int b = threadIdx.x; b < B_SZ; b += blockDim.x)
            g_hbuf[((size_t)(b >> 3) * 2 * 8 + (b & 7)) * H_SZ + p] = h0[(size_t)b * H_SZ + p];
    }
    if (p < NG * NC && threadIdx.x == 0) g_flags[p] = 0;
}

// ---------------- phase 1: gates_x GEMM  C[m][p] = A[m][:] . Wp[p][:] + bias[p] ----------------
#define BM 128
#define BN 64
#define BK 16
#define LDA (BM + 4)
#define LDB (BN + 4)

__global__ __launch_bounds__(256) void gemm_x_kernel(const float* __restrict__ A) {
    __shared__ float sA[BK][LDA];
    __shared__ float sB[BK][LDB];
    int tid   = threadIdx.x;
    int mBase = blockIdx.y * BM;
    int nBase = blockIdx.x * BN;
    int tm = tid & 15, tn = tid >> 4;

    int aM0 = tid >> 2;
    int aK0 = (tid & 3) * 4;
    int bN  = tid >> 2;
    int bK  = (tid & 3) * 4;

    const float* Ag = A + (size_t)mBase * I_SZ;
    const float* Bg = g_wih_p + (size_t)nBase * I_SZ;

    float4 ra0 = *(const float4*)(Ag + (size_t)aM0 * I_SZ + aK0);
    float4 ra1 = *(const float4*)(Ag + (size_t)(aM0 + 64) * I_SZ + aK0);
    float4 rb  = *(const float4*)(Bg + (size_t)bN * I_SZ + bK);

    ull acc[4][4];
#pragma unroll
    for (int u = 0; u < 4; u++)
#pragma unroll
        for (int j = 0; j < 4; j++) acc[u][j] = 0ull;

    const int KT = I_SZ / BK;
    for (int kt = 0; kt < KT; kt++) {
        sA[aK0 + 0][aM0] = ra0.x; sA[aK0 + 1][aM0] = ra0.y;
        sA[aK0 + 2][aM0] = ra0.z; sA[aK0 + 3][aM0] = ra0.w;
        sA[aK0 + 0][aM0 + 64] = ra1.x; sA[aK0 + 1][aM0 + 64] = ra1.y;
        sA[aK0 + 2][aM0 + 64] = ra1.z; sA[aK0 + 3][aM0 + 64] = ra1.w;
        sB[bK + 0][bN] = rb.x; sB[bK + 1][bN] = rb.y;
        sB[bK + 2][bN] = rb.z; sB[bK + 3][bN] = rb.w;
        __syncthreads();

        if (kt + 1 < KT) {
            int k0 = (kt + 1) * BK;
            ra0 = *(const float4*)(Ag + (size_t)aM0 * I_SZ + k0 + aK0);
            ra1 = *(const float4*)(Ag + (size_t)(aM0 + 64) * I_SZ + k0 + aK0);
            rb  = *(const float4*)(Bg + (size_t)bN * I_SZ + k0 + bK);
        }

#pragma unroll
        for (int kk = 0; kk < BK; kk++) {
            ulonglong2 a01 = *(const ulonglong2*)&sA[kk][tm * 8];
            ulonglong2 a23 = *(const ulonglong2*)&sA[kk][tm * 8 + 4];
            float4 b4 = *(const float4*)&sB[kk][tn * 4];
            ull b0 = pack2(b4.x), b1 = pack2(b4.y), b2 = pack2(b4.z), b3 = pack2(b4.w);
            ffma2(acc[0][0], a01.x, b0); ffma2(acc[0][1], a01.x, b1);
            ffma2(acc[0][2], a01.x, b2); ffma2(acc[0][3], a01.x, b3);
            ffma2(acc[1][0], a01.y, b0); ffma2(acc[1][1], a01.y, b1);
            ffma2(acc[1][2], a01.y, b2); ffma2(acc[1][3], a01.y, b3);
            ffma2(acc[2][0], a23.x, b0); ffma2(acc[2][1], a23.x, b1);
            ffma2(acc[2][2], a23.x, b2); ffma2(acc[2][3], a23.x, b3);
            ffma2(acc[3][0], a23.y, b0); ffma2(acc[3][1], a23.y, b1);
            ffma2(acc[3][2], a23.y, b2); ffma2(acc[3][3], a23.y, b3);
        }
        __syncthreads();
    }

    float4 bias = *(const float4*)&g_bias_p[nBase + tn * 4];
    float* C = g_gates + (size_t)(mBase + tm * 8) * G4 + nBase + tn * 4;
#pragma unroll
    for (int u = 0; u < 4; u++) {
        float2 c0 = unpack2(acc[u][0]);
        float2 c1 = unpack2(acc[u][1]);
        float2 c2 = unpack2(acc[u][2]);
        float2 c3 = unpack2(acc[u][3]);
        float4 lo = {c0.x + bias.x, c1.x + bias.y, c2.x + bias.z, c3.x + bias.w};
        float4 hi = {c0.y + bias.x, c1.y + bias.y, c2.y + bias.z, c3.y + bias.w};
        *(float4*)(C + (size_t)(2 * u) * G4)     = lo;
        *(float4*)(C + (size_t)(2 * u + 1) * G4) = hi;
    }
}

// ---------------- phase 2: persistent recurrent scan (flag-synced) ----------------
// 4 groups x 32 CTAs. Group grp owns batches [8g, 8g+8). CTA c owns packed rows
// [64c, 64c+64) (j in [16c, 16c+16)). Thread tid = rq*8 + b: rows {rq, rq+32},
// batch b, FULL K, acc = f32x2 over (k even, k odd). No pack2, no reduction.
// Gates of (jl, b) gathered by warp shuffle from lanes 8g'+b.
// Sync: ONLY warp 0 polls the 32 per-CTA flags (one coalesced 128B acquire load
// per poll) -> bar.sync releases the CTA. 8x less poll traffic than all-warp poll.
__global__ __launch_bounds__(256) void scan_kernel(const float* __restrict__ c0,
                                                   float* __restrict__ out, int out_size) {
    extern __shared__ float smem[];
    float* sh_w = smem;                 // 64 x WPITCH floats
    float* sh_h = smem + 64 * WPITCH;   // 8  x WPITCH floats

    int tid  = threadIdx.x;
    int grp  = blockIdx.x >> 5;
    int c    = blockIdx.x & 31;
    int lane = tid & 31, wid = tid >> 5;
    int rq   = tid >> 3;                // 0..31
    int b    = tid & 7;

    // W_hh slice -> padded SMEM (resident for all 1024 steps)
    {
        const float4* wsrc = (const float4*)(g_whh_p + (size_t)c * 64 * H_SZ);
#pragma unroll
        for (int i = 0; i < 32; i++) {
            int gi = tid + i * 256;          // float4 index, 0..8191
            int r = gi >> 7, k4 = gi & 127;
            *(float4*)(sh_w + r * WPITCH + k4 * 4) = __ldg(wsrc + gi);
        }
    }

    unsigned* flags = g_flags + grp * NC;
    float* hglob = g_hbuf + (size_t)grp * 2 * 8 * H_SZ;

    // epilogue role: lanes 0..15 of each warp each own one (j, b) output
    bool  epi = (lane < 16);
    int   eb  = lane & 7;
    int   ejl = wid + ((lane >> 3) & 1) * 8;   // 0..15
    int   ej  = c * 16 + ejl;
    int   ebg = grp * 8 + eb;
    float c_val = 0.f;
    const float4* gxp = (const float4*)g_gates;
    if (epi) {
        c_val = c0[(size_t)ebg * H_SZ + ej];
        gxp   = (const float4*)(g_gates + (size_t)ebg * G4 + c * 64 + ejl * 4);
    }
    __syncthreads();

    const float* wr0 = sh_w + rq * WPITCH;
    const float* wr1 = sh_w + (rq + 32) * WPITCH;
    const float* hrow = sh_h + b * WPITCH;

    for (int t = 0; t < T_STEPS; t++) {
        // prefetch gates_x (DRAM) before the wait — latency covered by poll
        float4 gxv = make_float4(0.f, 0.f, 0.f, 0.f);
        if (epi) gxv = __ldg(gxp + (size_t)t * (B_SZ * G4 / 4));

        // warp 0 waits for all 32 producers of h[t]; rest of CTA waits at bar
        if (wid == 0) {
            const unsigned* fp = flags + lane;
            for (;;) {
                unsigned v = ld_acq(fp);
                if (__all_sync(0xffffffffu, v >= (unsigned)t)) break;
            }
        }
        __syncthreads();

        // stage h[t] -> padded SMEM (L2-coherent loads)
        {
            const float4* hsrc = (const float4*)(hglob + (t & 1) * (8 * H_SZ));
#pragma unroll
            for (int i = 0; i < 4; i++) {
                int gi = tid + i * 256;      // float4 index, 0..1023
                int hb = gi >> 7, k4 = gi & 127;
                *(float4*)(sh_h + hb * WPITCH + k4 * 4) = __ldcg(hsrc + gi);
            }
        }
        __syncthreads();

        // dot products: rows {rq, rq+32} x batch b over K=512
        ull a00 = 0, a01 = 0, a10 = 0, a11 = 0;
#pragma unroll 8
        for (int k = 0; k < H_SZ; k += 4) {
            ulonglong2 w0 = *(const ulonglong2*)(wr0 + k);
            ulonglong2 w1 = *(const ulonglong2*)(wr1 + k);
            ulonglong2 hh = *(const ulonglong2*)(hrow + k);
            ffma2(a00, hh.x, w0.x); ffma2(a01, hh.y, w0.y);
            ffma2(a10, hh.x, w1.x); ffma2(a11, hh.y, w1.y);
        }
        fadd2(a00, a01); fadd2(a10, a11);
        float2 s1f = unpack2(a00), s2f = unpack2(a10);
        float s1 = s1f.x + s1f.y;     // row rq      (jl = wid,   gate rq&3)
        float s2 = s2f.x + s2f.y;     // row rq + 32 (jl = wid+8, gate rq&3)
        ull sv; asm("mov.b64 %0, {%1, %2};" : "=l"(sv) : "f"(s1), "f"(s2));

        int bl = lane & 7;
        ull q0 = __shfl_sync(0xffffffffu, sv, bl);
        ull q1 = __shfl_sync(0xffffffffu, sv, bl + 8);
        ull q2 = __shfl_sync(0xffffffffu, sv, bl + 16);
        ull q3 = __shfl_sync(0xffffffffu, sv, bl + 24);

        if (epi) {
            bool lo = (lane < 8);
            float2 G0 = unpack2(q0), G1 = unpack2(q1), G2 = unpack2(q2), G3 = unpack2(q3);
            float pi = (lo ? G0.x : G0.y) + gxv.x;
            float pf = (lo ? G1.x : G1.y) + gxv.y;
            float pg = (lo ? G2.x : G2.y) + gxv.z;
            float po = (lo ? G3.x : G3.y) + gxv.w;
            float ig = sigf(pi), fg = sigf(pf), og = sigf(po);
            float gg = tanh_fast(pg);
            c_val = fg * c_val + ig * gg;
            float hn = og * tanh_fast(c_val);
            hglob[((t + 1) & 1) * (8 * H_SZ) + eb * H_SZ + ej] = hn;
            out[(size_t)t * BH + (size_t)ebg * H_SZ + ej] = hn;
            if (t == T_STEPS - 1 && out_size >= TBH + 2 * BH) {
                out[TBH + ebg * H_SZ + ej]      = hn;     // h_f
                out[TBH + BH + ebg * H_SZ + ej] = c_val;  // c_f
            }
        }

        __syncthreads();                      // all warps' h stores done
        if (tid == 0) st_rel(&flags[c], (unsigned)(t + 1));
    }
}

// ---------------- launch ----------------
extern "C" void kernel_launch(void* const* d_in, const int* in_sizes, int n_in,
                              void* d_out, int out_size) {
    const float* input = (const float*)d_in[0];
    const float* h0    = (const float*)d_in[1];
    const float* c0    = (const float*)d_in[2];
    const float* Wih   = (const float*)d_in[3];
    const float* Whh   = (const float*)d_in[4];
    const float* bih   = (const float*)d_in[5];
    const float* bhh   = (const float*)d_in[6];
    float* out = (float*)d_out;

    prep_kernel<<<G4, 128>>>(Wih, Whh, bih, bhh, h0);

    dim3 grid(G4 / BN, (T_STEPS * B_SZ) / BM);
    gemm_x_kernel<<<grid, 256>>>(input);

    const int scan_smem = 72 * WPITCH * (int)sizeof(float);  // 148608 B
    cudaFuncSetAttribute(scan_kernel, cudaFuncAttributeMaxDynamicSharedMemorySize, scan_smem);
    scan_kernel<<<NG * NC, 256, scan_smem>>>(c0, out, out_size);
}